// round 9
// baseline (speedup 1.0000x reference)
#include <cuda_runtime.h>
#include <cstdint>

#define NTH   1024
#define KSEL  100
#define NBINS 4096
#define CAP   2048
#define FULLM 0xffffffffu

// smem layout sizes (same as R4)
#define SM_CAND   (CAP * 8)            // 16384
#define SM_KEYS   (16384 * 4)          // 65536
#define SM_HIST   (NBINS * 4)          // 16384
#define SM_ROWS   (KSEL*16*4 + KSEL*4*4 + 7*KSEL*4 + 32)
#define SMEM_BYTES (SM_CAND + SM_KEYS + SM_HIST + SM_ROWS)

__device__ __forceinline__ unsigned fkey(float f) {
    unsigned u = __float_as_uint(f);
    return (u & 0x80000000u) ? ~u : (u | 0x80000000u);
}

__global__ __launch_bounds__(NTH) void pp_kernel(
    const float* __restrict__ blk_logit,
    const float* __restrict__ lin_logit,
    const float* __restrict__ chr_logit,
    const float* __restrict__ blk_raw,
    const float* __restrict__ lin_raw,
    const float* __restrict__ chr_raw,
    const float* __restrict__ tsz,
    float* __restrict__ out,
    int B, int NB, int NL, int NC)
{
    // Tail-balanced remap: heavy CTAs (lvl1/lvl2) first, light lvl0 in the tail wave.
    const int bid = blockIdx.x;
    int b, lvl;
    if (bid < 2 * B) { lvl = 1 + (bid & 1); b = bid >> 1; }
    else             { lvl = 0; b = bid - 2 * B; }
    const int tid = threadIdx.x;

    int N, PN = 0, ef = 1;
    const float *logit, *raw, *praw = nullptr;
    bool bez = false;
    if (lvl == 0)      { N = NB; logit = blk_logit; raw = blk_raw; }
    else if (lvl == 1) { N = NL; logit = lin_logit; raw = lin_raw; praw = blk_raw; PN = NB; ef = 4; }
    else               { N = NC; logit = chr_logit; raw = chr_raw; praw = lin_raw; PN = NL; ef = 1; bez = true; }

    extern __shared__ unsigned char sm[];
    unsigned long long* cand = (unsigned long long*)sm;
    unsigned* keys = (unsigned*)(sm + SM_CAND);
    unsigned* hist = (unsigned*)(sm + SM_CAND + SM_KEYS);
    unsigned char* p = sm + SM_CAND + SM_KEYS + SM_HIST;
    float* s_data = (float*)p; p += KSEL * 16 * 4;
    float* s_box  = (float*)p; p += KSEL * 4 * 4;
    float* s_val  = (float*)p; p += KSEL * 4;
    float* s_bel  = (float*)p; p += KSEL * 4;
    float* s_area = (float*)p; p += KSEL * 4;
    int*   s_keep = (int*)p;   p += KSEL * 4;
    int*   s_vld  = (int*)p;   p += KSEL * 4;
    int*   s_nk   = (int*)p;   p += KSEL * 4;
    int*   s_T    = (int*)p;   p += 4;
    unsigned* s_cnt = (unsigned*)p;

    for (int i = tid; i < NBINS; i += NTH) hist[i] = 0;
    if (tid == 0) *s_cnt = 0;
    __syncthreads();

    // ---- Pass 1: float4 loads, monotonic keys -> smem, per-element histogram ----
    const float4* lp4 = (const float4*)(logit + (size_t)b * N);
    const int n4 = N >> 2;
    for (int i = tid; i < n4; i += NTH) {
        float4 v = lp4[i];
        unsigned k0 = fkey(v.x), k1 = fkey(v.y), k2 = fkey(v.z), k3 = fkey(v.w);
        ((uint4*)keys)[i] = make_uint4(k0, k1, k2, k3);
        atomicAdd(&hist[k0 >> 20], 1u);
        atomicAdd(&hist[k1 >> 20], 1u);
        atomicAdd(&hist[k2 >> 20], 1u);
        atomicAdd(&hist[k3 >> 20], 1u);
    }
    __syncthreads();

    // ---- Per-thread chunk sums (4 bins each), alias psum onto cand area ----
    unsigned* psum = (unsigned*)cand;   // 1024 entries
    {
        unsigned s = 0;
        int base = tid * (NBINS / NTH);
        #pragma unroll
        for (int j = 0; j < NBINS / NTH; ++j) s += hist[base + j];
        psum[tid] = s;
    }
    __syncthreads();

    // ---- Warp 0: find largest bin T with count(bins >= T) >= KSEL ----
    if (tid < 32) {
        const int lane = tid;
        unsigned carry = 0;
        for (int g = 31; g >= 0; --g) {
            unsigned v = psum[g * 32 + lane];
            unsigned s = v;
            #pragma unroll
            for (int off = 1; off < 32; off <<= 1) {
                unsigned n = __shfl_down_sync(FULLM, s, off);
                if (lane + off < 32) s += n;
            }
            unsigned gsum = __shfl_sync(FULLM, s, 0);
            if (carry + gsum >= (unsigned)KSEL) {
                unsigned ball = __ballot_sync(FULLM, carry + s >= (unsigned)KSEL);
                int hi = 31 - __clz(ball);
                unsigned s_hi = __shfl_sync(FULLM, s, hi);
                unsigned v_hi = __shfl_sync(FULLM, v, hi);
                if (lane == 0) {
                    unsigned above = carry + s_hi - v_hi;  // count of chunks > C
                    int C = g * 32 + hi;                   // chunk of 4 bins
                    int T = C * 4;
                    for (int w = 3; w >= 0; --w) {
                        above += hist[C * 4 + w];
                        if (above >= (unsigned)KSEL) { T = C * 4 + w; break; }
                    }
                    *s_T = T;
                }
                break;
            }
            carry += gsum;
        }
    }
    __syncthreads();
    const unsigned T = (unsigned)*s_T;

    // ---- Collect candidates with bin >= T (R4 verbatim) ----
    for (int i = tid; i < N; i += NTH) {
        unsigned key = keys[i];
        if ((key >> 20) >= T) {
            unsigned pos = atomicAdd(s_cnt, 1u);
            if (pos < CAP)
                cand[pos] = ((unsigned long long)key << 32) | (unsigned)(~i);
        }
    }
    __syncthreads();
    int cnt = (int)*s_cnt; if (cnt > CAP) cnt = CAP;
    int P = 128; while (P < cnt) P <<= 1;
    for (int i = tid; i < P; i += NTH) if (i >= cnt) cand[i] = 0ULL;
    __syncthreads();

    // ---- Bitonic sort descending (composite = (key, ~idx): stable lower-index first) ----
    for (int k = 2; k <= P; k <<= 1) {
        for (int j = k >> 1; j > 0; j >>= 1) {
            for (int i = tid; i < P; i += NTH) {
                int ixj = i ^ j;
                if (ixj > i) {
                    unsigned long long a = cand[i], c2 = cand[ixj];
                    bool desc = ((i & k) == 0);
                    if (desc ? (a < c2) : (a > c2)) { cand[i] = c2; cand[ixj] = a; }
                }
            }
            __syncthreads();
        }
    }

    const float ih = tsz[2 * b + 0];  // target h
    const float iw = tsz[2 * b + 1];  // target w

    // ---- Per-row decode (R4 verbatim) ----
    if (tid < KSEL) {
        unsigned long long e = cand[tid];
        unsigned key = (unsigned)(e >> 32);
        int idx = (int)(~((unsigned)e));
        unsigned u = (key & 0x80000000u) ? (key ^ 0x80000000u) : ~key;
        float lg = __uint_as_float(u);
        float prob = 1.0f / (1.0f + expf(-lg));
        s_val[tid] = prob;
        s_keep[tid] = prob > 0.1f;

        float bx0, bx1, bx2, bx3;
        if (!bez) {
            const float* rp = raw + ((size_t)b * N + idx) * 4;
            float cx = rp[0], cy = rp[1], bw = rp[2], bh = rp[3];
            bx0 = (cx - 0.5f * bw) * iw;
            bx1 = (cy - 0.5f * bh) * ih;
            bx2 = (cx + 0.5f * bw) * iw;
            bx3 = (cy + 0.5f * bh) * ih;
            if (lvl == 0) {
                bx0 = fminf(fmaxf(bx0, 0.f), iw);
                bx1 = fminf(fmaxf(bx1, 0.f), ih);
                bx2 = fminf(fmaxf(bx2, 0.f), iw);
                bx3 = fminf(fmaxf(bx3, 0.f), ih);
            }
            s_data[tid * 16 + 0] = bx0; s_data[tid * 16 + 1] = bx1;
            s_data[tid * 16 + 2] = bx2; s_data[tid * 16 + 3] = bx3;
        } else {
            const float* rp = raw + ((size_t)b * N + idx) * 16;
            float cpt[16];
            #pragma unroll
            for (int q = 0; q < 8; ++q) {
                cpt[2 * q + 0] = rp[2 * q + 0] * ih;   // tile(tsize,8): even -> h
                cpt[2 * q + 1] = rp[2 * q + 1] * iw;   // odd -> w
            }
            #pragma unroll
            for (int q = 0; q < 16; ++q) s_data[tid * 16 + q] = cpt[q];
            float mn0 = 1e30f, mn1 = 1e30f, mx0 = -1e30f, mx1 = -1e30f;
            #pragma unroll
            for (int s2 = 0; s2 < 10; ++s2) {
                float t  = (float)s2 / 9.0f;
                float ti = 1.0f - t;
                float b0 = ti * ti * ti, b1 = 3.f * t * ti * ti;
                float b2 = 3.f * t * t * ti, b3 = t * t * t;
                float p0 = b0 * cpt[0] + b1 * cpt[2] + b2 * cpt[4]  + b3 * cpt[6];
                float p1 = b0 * cpt[1] + b1 * cpt[3] + b2 * cpt[5]  + b3 * cpt[7];
                float q0 = b0 * cpt[8] + b1 * cpt[10] + b2 * cpt[12] + b3 * cpt[14];
                float q1 = b0 * cpt[9] + b1 * cpt[11] + b2 * cpt[13] + b3 * cpt[15];
                mn0 = fminf(mn0, fminf(p0, q0));
                mn1 = fminf(mn1, fminf(p1, q1));
                mx0 = fmaxf(mx0, fmaxf(p0, q0));
                mx1 = fmaxf(mx1, fmaxf(p1, q1));
            }
            bx0 = mn0; bx1 = mn1; bx2 = mx0; bx3 = mx1;
        }
        s_box[tid * 4 + 0] = bx0; s_box[tid * 4 + 1] = bx1;
        s_box[tid * 4 + 2] = bx2; s_box[tid * 4 + 3] = bx3;
        float area = (bx2 - bx0) * (bx3 - bx1);
        s_area[tid] = area;

        if (lvl > 0) {
            const float* pr = praw + ((size_t)b * PN + idx / ef) * 4;
            float pcx = pr[0], pcy = pr[1], pw = pr[2], ph = pr[3];
            float px0 = (pcx - 0.5f * pw) * iw, py0 = (pcy - 0.5f * ph) * ih;
            float px1 = (pcx + 0.5f * pw) * iw, py1 = (pcy + 0.5f * ph) * ih;
            float ix1 = fmaxf(bx0, px0), iy1 = fmaxf(bx1, py0);
            float ix2 = fminf(bx2, px1), iy2 = fminf(bx3, py1);
            float inter = fmaxf(ix2 - ix1, 0.f) * fmaxf(iy2 - iy1, 0.f);
            float belong = inter / (area + 1e-6f);
            s_bel[tid] = belong;
            s_vld[tid] = belong > 0.6f;
        }
    }
    __syncthreads();

    // ---- Serial reductions (tid 0; R4 verbatim — empirically the fast path) ----
    if (tid == 0) {
        bool any = false;
        for (int r = 0; r < KSEL; ++r) any = any || (s_keep[r] != 0);
        if (!any) s_keep[0] = 1;
        if (lvl > 0) {
            bool anyVK = false;
            float best = -1e38f; int bi = 0;
            for (int r = 0; r < KSEL; ++r) {
                bool kp = s_keep[r] != 0;
                if (kp && s_vld[r]) anyVK = true;
                float v2 = kp ? s_bel[r] : -1e38f;
                if (v2 > best) { best = v2; bi = r; }
            }
            for (int r = 0; r < KSEL; ++r) {
                int m = anyVK ? (s_keep[r] && s_vld[r])
                              : (s_keep[r] && (r == bi));
                s_nk[r] = m;
            }
        } else {
            for (int r = 0; r < KSEL; ++r) s_nk[r] = s_keep[r];
        }
    }

    // ---- Greedy NMS (sequential over i; columns parallel; R4 verbatim) ----
    for (int i = 0; i < KSEL - 1; ++i) {
        __syncthreads();
        if (tid > i && tid < KSEL && s_nk[i]) {
            float ax0 = s_box[i * 4 + 0], ay0 = s_box[i * 4 + 1];
            float ax1 = s_box[i * 4 + 2], ay1 = s_box[i * 4 + 3];
            float bx0 = s_box[tid * 4 + 0], by0 = s_box[tid * 4 + 1];
            float bx1 = s_box[tid * 4 + 2], by1 = s_box[tid * 4 + 3];
            float ix0 = fmaxf(ax0, bx0), iy0 = fmaxf(ay0, by0);
            float ix1 = fminf(ax1, bx1), iy1 = fminf(ay1, by1);
            float inter = fmaxf(ix1 - ix0, 0.f) * fmaxf(iy1 - iy0, 0.f);
            float iou = inter / (s_area[i] + s_area[tid] - inter);
            if (iou > 0.1f) s_nk[tid] = 0;
        }
    }
    __syncthreads();

    // ---- Write outputs (R4 verbatim) ----
    size_t nbd = (size_t)B * 400;   // B*100*4
    size_t nsc = (size_t)B * 100;
    size_t oD, oS, oK;
    if (lvl == 0)      { oD = 0; oS = nbd; oK = nbd + nsc; }
    else if (lvl == 1) { size_t base = nbd + 2 * nsc; oD = base; oS = base + nbd; oK = oS + nsc; }
    else               { size_t base = 2 * (nbd + 2 * nsc); oD = base; oS = base + (size_t)B * 1600; oK = oS + nsc; }

    if (tid < KSEL) {
        bool nk = s_nk[tid] != 0;
        out[oS + (size_t)b * 100 + tid] = nk ? s_val[tid] : 0.f;
        out[oK + (size_t)b * 100 + tid] = nk ? 1.f : 0.f;
        int D = bez ? 16 : 4;
        float* dp = out + oD + ((size_t)b * 100 + tid) * D;
        for (int d2 = 0; d2 < D; ++d2) dp[d2] = nk ? s_data[tid * 16 + d2] : 0.f;
    }
}

extern "C" void kernel_launch(void* const* d_in, const int* in_sizes, int n_in,
                              void* d_out, int out_size) {
    const float* blk_logit = (const float*)d_in[0];
    const float* lin_logit = (const float*)d_in[1];
    const float* chr_logit = (const float*)d_in[2];
    const float* blk_raw   = (const float*)d_in[3];
    const float* lin_raw   = (const float*)d_in[4];
    const float* chr_raw   = (const float*)d_in[5];
    const float* tsz       = (const float*)d_in[6];
    float* out = (float*)d_out;

    int B  = in_sizes[6] / 2;
    int NB = in_sizes[0] / B;
    int NL = in_sizes[1] / B;
    int NC = in_sizes[2] / B;

    cudaFuncSetAttribute(pp_kernel, cudaFuncAttributeMaxDynamicSharedMemorySize, SMEM_BYTES);
    pp_kernel<<<3 * B, NTH, SMEM_BYTES>>>(blk_logit, lin_logit, chr_logit,
                                          blk_raw, lin_raw, chr_raw, tsz, out,
                                          B, NB, NL, NC);
}

// round 10
// speedup vs baseline: 1.7008x; 1.7008x over previous
#include <cuda_runtime.h>
#include <cstdint>

#define NTH   512
#define KSEL  100
#define NBINS 4096
#define CAP   2048
#define FULLM 0xffffffffu

// smem layout sizes (same as R4)
#define SM_CAND   (CAP * 8)            // 16384
#define SM_KEYS   (16384 * 4)          // 65536
#define SM_HIST   (NBINS * 4)          // 16384
#define SM_ROWS   (KSEL*16*4 + KSEL*4*4 + 7*KSEL*4 + 32)
#define SMEM_BYTES (SM_CAND + SM_KEYS + SM_HIST + SM_ROWS)

__device__ __forceinline__ unsigned fkey(float f) {
    unsigned u = __float_as_uint(f);
    return (u & 0x80000000u) ? ~u : (u | 0x80000000u);
}

__global__ __launch_bounds__(NTH) void pp_kernel(
    const float* __restrict__ blk_logit,
    const float* __restrict__ lin_logit,
    const float* __restrict__ chr_logit,
    const float* __restrict__ blk_raw,
    const float* __restrict__ lin_raw,
    const float* __restrict__ chr_raw,
    const float* __restrict__ tsz,
    float* __restrict__ out,
    int B, int NB, int NL, int NC)
{
    // Tail-balanced remap: heavy CTAs (lvl1/lvl2) first, light lvl0 in the tail wave.
    const int bid = blockIdx.x;
    int b, lvl;
    if (bid < 2 * B) { lvl = 1 + (bid & 1); b = bid >> 1; }
    else             { lvl = 0; b = bid - 2 * B; }
    const int tid = threadIdx.x;

    int N, PN = 0, ef = 1;
    const float *logit, *raw, *praw = nullptr;
    bool bez = false;
    if (lvl == 0)      { N = NB; logit = blk_logit; raw = blk_raw; }
    else if (lvl == 1) { N = NL; logit = lin_logit; raw = lin_raw; praw = blk_raw; PN = NB; ef = 4; }
    else               { N = NC; logit = chr_logit; raw = chr_raw; praw = lin_raw; PN = NL; ef = 1; bez = true; }

    extern __shared__ unsigned char sm[];
    unsigned long long* cand = (unsigned long long*)sm;
    unsigned* keys = (unsigned*)(sm + SM_CAND);
    unsigned* hist = (unsigned*)(sm + SM_CAND + SM_KEYS);
    unsigned char* p = sm + SM_CAND + SM_KEYS + SM_HIST;
    float* s_data = (float*)p; p += KSEL * 16 * 4;
    float* s_box  = (float*)p; p += KSEL * 4 * 4;
    float* s_val  = (float*)p; p += KSEL * 4;
    float* s_bel  = (float*)p; p += KSEL * 4;
    float* s_area = (float*)p; p += KSEL * 4;
    int*   s_keep = (int*)p;   p += KSEL * 4;
    int*   s_vld  = (int*)p;   p += KSEL * 4;
    int*   s_nk   = (int*)p;   p += KSEL * 4;
    int*   s_T    = (int*)p;   p += 4;
    unsigned* s_cnt = (unsigned*)p;

    for (int i = tid; i < NBINS; i += NTH) hist[i] = 0;
    if (tid == 0) *s_cnt = 0;
    __syncthreads();

    // ---- Pass 1: float4 loads, monotonic keys -> smem, per-element histogram ----
    const float4* lp4 = (const float4*)(logit + (size_t)b * N);
    const int n4 = N >> 2;
    for (int i = tid; i < n4; i += NTH) {
        float4 v = lp4[i];
        unsigned k0 = fkey(v.x), k1 = fkey(v.y), k2 = fkey(v.z), k3 = fkey(v.w);
        ((uint4*)keys)[i] = make_uint4(k0, k1, k2, k3);
        atomicAdd(&hist[k0 >> 20], 1u);
        atomicAdd(&hist[k1 >> 20], 1u);
        atomicAdd(&hist[k2 >> 20], 1u);
        atomicAdd(&hist[k3 >> 20], 1u);
    }
    __syncthreads();

    // ---- Per-thread chunk sums (8 bins each), alias psum onto cand area ----
    unsigned* psum = (unsigned*)cand;
    {
        unsigned s = 0;
        int base = tid * (NBINS / NTH);
        #pragma unroll
        for (int j = 0; j < NBINS / NTH; ++j) s += hist[base + j];
        psum[tid] = s;
    }
    __syncthreads();

    // ---- Warp 0: find largest bin T with count(bins >= T) >= KSEL ----
    if (tid < 32) {
        const int lane = tid;
        unsigned carry = 0;
        for (int g = 15; g >= 0; --g) {
            unsigned v = psum[g * 32 + lane];
            unsigned s = v;
            #pragma unroll
            for (int off = 1; off < 32; off <<= 1) {
                unsigned n = __shfl_down_sync(FULLM, s, off);
                if (lane + off < 32) s += n;
            }
            unsigned gsum = __shfl_sync(FULLM, s, 0);
            if (carry + gsum >= (unsigned)KSEL) {
                unsigned ball = __ballot_sync(FULLM, carry + s >= (unsigned)KSEL);
                int hi = 31 - __clz(ball);
                unsigned s_hi = __shfl_sync(FULLM, s, hi);
                unsigned v_hi = __shfl_sync(FULLM, v, hi);
                if (lane == 0) {
                    unsigned above = carry + s_hi - v_hi;  // count of chunks > C
                    int C = g * 32 + hi;
                    int T = C * 8;
                    for (int w = 7; w >= 0; --w) {
                        above += hist[C * 8 + w];
                        if (above >= (unsigned)KSEL) { T = C * 8 + w; break; }
                    }
                    *s_T = T;
                }
                break;
            }
            carry += gsum;
        }
    }
    __syncthreads();
    const unsigned T = (unsigned)*s_T;

    // ---- Collect candidates with bin >= T (R4 verbatim) ----
    for (int i = tid; i < N; i += NTH) {
        unsigned key = keys[i];
        if ((key >> 20) >= T) {
            unsigned pos = atomicAdd(s_cnt, 1u);
            if (pos < CAP)
                cand[pos] = ((unsigned long long)key << 32) | (unsigned)(~i);
        }
    }
    __syncthreads();
    int cnt = (int)*s_cnt; if (cnt > CAP) cnt = CAP;
    int P = 128; while (P < cnt) P <<= 1;
    for (int i = tid; i < P; i += NTH) if (i >= cnt) cand[i] = 0ULL;
    __syncthreads();

    // ---- Bitonic sort descending (composite = (key, ~idx): stable lower-index first) ----
    for (int k = 2; k <= P; k <<= 1) {
        for (int j = k >> 1; j > 0; j >>= 1) {
            for (int i = tid; i < P; i += NTH) {
                int ixj = i ^ j;
                if (ixj > i) {
                    unsigned long long a = cand[i], c2 = cand[ixj];
                    bool desc = ((i & k) == 0);
                    if (desc ? (a < c2) : (a > c2)) { cand[i] = c2; cand[ixj] = a; }
                }
            }
            __syncthreads();
        }
    }

    const float ih = tsz[2 * b + 0];  // target h
    const float iw = tsz[2 * b + 1];  // target w

    // ---- Per-row decode (R4 verbatim) ----
    if (tid < KSEL) {
        unsigned long long e = cand[tid];
        unsigned key = (unsigned)(e >> 32);
        int idx = (int)(~((unsigned)e));
        unsigned u = (key & 0x80000000u) ? (key ^ 0x80000000u) : ~key;
        float lg = __uint_as_float(u);
        float prob = 1.0f / (1.0f + expf(-lg));
        s_val[tid] = prob;
        s_keep[tid] = prob > 0.1f;

        float bx0, bx1, bx2, bx3;
        if (!bez) {
            const float* rp = raw + ((size_t)b * N + idx) * 4;
            float cx = rp[0], cy = rp[1], bw = rp[2], bh = rp[3];
            bx0 = (cx - 0.5f * bw) * iw;
            bx1 = (cy - 0.5f * bh) * ih;
            bx2 = (cx + 0.5f * bw) * iw;
            bx3 = (cy + 0.5f * bh) * ih;
            if (lvl == 0) {
                bx0 = fminf(fmaxf(bx0, 0.f), iw);
                bx1 = fminf(fmaxf(bx1, 0.f), ih);
                bx2 = fminf(fmaxf(bx2, 0.f), iw);
                bx3 = fminf(fmaxf(bx3, 0.f), ih);
            }
            s_data[tid * 16 + 0] = bx0; s_data[tid * 16 + 1] = bx1;
            s_data[tid * 16 + 2] = bx2; s_data[tid * 16 + 3] = bx3;
        } else {
            const float* rp = raw + ((size_t)b * N + idx) * 16;
            float cpt[16];
            #pragma unroll
            for (int q = 0; q < 8; ++q) {
                cpt[2 * q + 0] = rp[2 * q + 0] * ih;   // tile(tsize,8): even -> h
                cpt[2 * q + 1] = rp[2 * q + 1] * iw;   // odd -> w
            }
            #pragma unroll
            for (int q = 0; q < 16; ++q) s_data[tid * 16 + q] = cpt[q];
            float mn0 = 1e30f, mn1 = 1e30f, mx0 = -1e30f, mx1 = -1e30f;
            #pragma unroll
            for (int s2 = 0; s2 < 10; ++s2) {
                float t  = (float)s2 / 9.0f;
                float ti = 1.0f - t;
                float b0 = ti * ti * ti, b1 = 3.f * t * ti * ti;
                float b2 = 3.f * t * t * ti, b3 = t * t * t;
                float p0 = b0 * cpt[0] + b1 * cpt[2] + b2 * cpt[4]  + b3 * cpt[6];
                float p1 = b0 * cpt[1] + b1 * cpt[3] + b2 * cpt[5]  + b3 * cpt[7];
                float q0 = b0 * cpt[8] + b1 * cpt[10] + b2 * cpt[12] + b3 * cpt[14];
                float q1 = b0 * cpt[9] + b1 * cpt[11] + b2 * cpt[13] + b3 * cpt[15];
                mn0 = fminf(mn0, fminf(p0, q0));
                mn1 = fminf(mn1, fminf(p1, q1));
                mx0 = fmaxf(mx0, fmaxf(p0, q0));
                mx1 = fmaxf(mx1, fmaxf(p1, q1));
            }
            bx0 = mn0; bx1 = mn1; bx2 = mx0; bx3 = mx1;
        }
        s_box[tid * 4 + 0] = bx0; s_box[tid * 4 + 1] = bx1;
        s_box[tid * 4 + 2] = bx2; s_box[tid * 4 + 3] = bx3;
        float area = (bx2 - bx0) * (bx3 - bx1);
        s_area[tid] = area;

        if (lvl > 0) {
            const float* pr = praw + ((size_t)b * PN + idx / ef) * 4;
            float pcx = pr[0], pcy = pr[1], pw = pr[2], ph = pr[3];
            float px0 = (pcx - 0.5f * pw) * iw, py0 = (pcy - 0.5f * ph) * ih;
            float px1 = (pcx + 0.5f * pw) * iw, py1 = (pcy + 0.5f * ph) * ih;
            float ix1 = fmaxf(bx0, px0), iy1 = fmaxf(bx1, py0);
            float ix2 = fminf(bx2, px1), iy2 = fminf(bx3, py1);
            float inter = fmaxf(ix2 - ix1, 0.f) * fmaxf(iy2 - iy1, 0.f);
            float belong = inter / (area + 1e-6f);
            s_bel[tid] = belong;
            s_vld[tid] = belong > 0.6f;
        }
    }
    __syncthreads();

    // ---- Serial reductions (tid 0; R4 verbatim — empirically the fast path) ----
    if (tid == 0) {
        bool any = false;
        for (int r = 0; r < KSEL; ++r) any = any || (s_keep[r] != 0);
        if (!any) s_keep[0] = 1;
        if (lvl > 0) {
            bool anyVK = false;
            float best = -1e38f; int bi = 0;
            for (int r = 0; r < KSEL; ++r) {
                bool kp = s_keep[r] != 0;
                if (kp && s_vld[r]) anyVK = true;
                float v2 = kp ? s_bel[r] : -1e38f;
                if (v2 > best) { best = v2; bi = r; }
            }
            for (int r = 0; r < KSEL; ++r) {
                int m = anyVK ? (s_keep[r] && s_vld[r])
                              : (s_keep[r] && (r == bi));
                s_nk[r] = m;
            }
        } else {
            for (int r = 0; r < KSEL; ++r) s_nk[r] = s_keep[r];
        }
    }
    __syncthreads();   // s_nk visible to the NMS subset

    // ---- Greedy NMS on warps 0-3 only (named barrier 1, 128 threads);
    //      warps 4-15 wait at the following block-wide barrier ----
    if (tid < 128) {
        for (int i = 0; i < KSEL - 1; ++i) {
            asm volatile("bar.sync 1, 128;" ::: "memory");
            if (tid > i && tid < KSEL && s_nk[i]) {
                float ax0 = s_box[i * 4 + 0], ay0 = s_box[i * 4 + 1];
                float ax1 = s_box[i * 4 + 2], ay1 = s_box[i * 4 + 3];
                float bx0 = s_box[tid * 4 + 0], by0 = s_box[tid * 4 + 1];
                float bx1 = s_box[tid * 4 + 2], by1 = s_box[tid * 4 + 3];
                float ix0 = fmaxf(ax0, bx0), iy0 = fmaxf(ay0, by0);
                float ix1 = fminf(ax1, bx1), iy1 = fminf(ay1, by1);
                float inter = fmaxf(ix1 - ix0, 0.f) * fmaxf(iy1 - iy0, 0.f);
                float iou = inter / (s_area[i] + s_area[tid] - inter);
                if (iou > 0.1f) s_nk[tid] = 0;
            }
        }
    }
    __syncthreads();

    // ---- Write outputs (R4 verbatim) ----
    size_t nbd = (size_t)B * 400;   // B*100*4
    size_t nsc = (size_t)B * 100;
    size_t oD, oS, oK;
    if (lvl == 0)      { oD = 0; oS = nbd; oK = nbd + nsc; }
    else if (lvl == 1) { size_t base = nbd + 2 * nsc; oD = base; oS = base + nbd; oK = oS + nsc; }
    else               { size_t base = 2 * (nbd + 2 * nsc); oD = base; oS = base + (size_t)B * 1600; oK = oS + nsc; }

    if (tid < KSEL) {
        bool nk = s_nk[tid] != 0;
        out[oS + (size_t)b * 100 + tid] = nk ? s_val[tid] : 0.f;
        out[oK + (size_t)b * 100 + tid] = nk ? 1.f : 0.f;
        int D = bez ? 16 : 4;
        float* dp = out + oD + ((size_t)b * 100 + tid) * D;
        for (int d2 = 0; d2 < D; ++d2) dp[d2] = nk ? s_data[tid * 16 + d2] : 0.f;
    }
}

extern "C" void kernel_launch(void* const* d_in, const int* in_sizes, int n_in,
                              void* d_out, int out_size) {
    const float* blk_logit = (const float*)d_in[0];
    const float* lin_logit = (const float*)d_in[1];
    const float* chr_logit = (const float*)d_in[2];
    const float* blk_raw   = (const float*)d_in[3];
    const float* lin_raw   = (const float*)d_in[4];
    const float* chr_raw   = (const float*)d_in[5];
    const float* tsz       = (const float*)d_in[6];
    float* out = (float*)d_out;

    int B  = in_sizes[6] / 2;
    int NB = in_sizes[0] / B;
    int NL = in_sizes[1] / B;
    int NC = in_sizes[2] / B;

    cudaFuncSetAttribute(pp_kernel, cudaFuncAttributeMaxDynamicSharedMemorySize, SMEM_BYTES);
    pp_kernel<<<3 * B, NTH, SMEM_BYTES>>>(blk_logit, lin_logit, chr_logit,
                                          blk_raw, lin_raw, chr_raw, tsz, out,
                                          B, NB, NL, NC);
}

// round 12
// speedup vs baseline: 1.9093x; 1.1226x over previous
#include <cuda_runtime.h>
#include <cstdint>

#define NTH   512
#define KSEL  100
#define NBINS 4096
#define CAP   2048
#define FULLM 0xffffffffu

// smem layout sizes (same as R4)
#define SM_CAND   (CAP * 8)            // 16384
#define SM_KEYS   (16384 * 4)          // 65536
#define SM_HIST   (NBINS * 4)          // 16384
#define SM_ROWS   (KSEL*16*4 + KSEL*4*4 + 7*KSEL*4 + 32)
#define SMEM_BYTES (SM_CAND + SM_KEYS + SM_HIST + SM_ROWS)

__device__ __forceinline__ unsigned fkey(float f) {
    unsigned u = __float_as_uint(f);
    return (u & 0x80000000u) ? ~u : (u | 0x80000000u);
}

__global__ __launch_bounds__(NTH) void pp_kernel(
    const float* __restrict__ blk_logit,
    const float* __restrict__ lin_logit,
    const float* __restrict__ chr_logit,
    const float* __restrict__ blk_raw,
    const float* __restrict__ lin_raw,
    const float* __restrict__ chr_raw,
    const float* __restrict__ tsz,
    float* __restrict__ out,
    int B, int NB, int NL, int NC)
{
    // Tail-balanced remap: heavy CTAs (lvl1/lvl2) first, light lvl0 in the tail wave.
    const int bid = blockIdx.x;
    int b, lvl;
    if (bid < 2 * B) { lvl = 1 + (bid & 1); b = bid >> 1; }
    else             { lvl = 0; b = bid - 2 * B; }
    const int tid = threadIdx.x;

    int N, PN = 0, ef = 1;
    const float *logit, *raw, *praw = nullptr;
    bool bez = false;
    if (lvl == 0)      { N = NB; logit = blk_logit; raw = blk_raw; }
    else if (lvl == 1) { N = NL; logit = lin_logit; raw = lin_raw; praw = blk_raw; PN = NB; ef = 4; }
    else               { N = NC; logit = chr_logit; raw = chr_raw; praw = lin_raw; PN = NL; ef = 1; bez = true; }

    extern __shared__ unsigned char sm[];
    unsigned long long* cand = (unsigned long long*)sm;
    unsigned* keys = (unsigned*)(sm + SM_CAND);
    unsigned* hist = (unsigned*)(sm + SM_CAND + SM_KEYS);
    unsigned char* p = sm + SM_CAND + SM_KEYS + SM_HIST;
    float* s_data = (float*)p; p += KSEL * 16 * 4;
    float* s_box  = (float*)p; p += KSEL * 4 * 4;
    float* s_val  = (float*)p; p += KSEL * 4;
    float* s_bel  = (float*)p; p += KSEL * 4;
    float* s_area = (float*)p; p += KSEL * 4;
    int*   s_keep = (int*)p;   p += KSEL * 4;
    int*   s_vld  = (int*)p;   p += KSEL * 4;
    int*   s_nk   = (int*)p;   p += KSEL * 4;
    int*   s_T    = (int*)p;   p += 4;
    unsigned* s_cnt = (unsigned*)p;

    for (int i = tid; i < NBINS; i += NTH) hist[i] = 0;
    if (tid == 0) *s_cnt = 0;
    __syncthreads();

    // ---- Pass 1: float4 loads, monotonic keys -> smem, per-element histogram ----
    const float4* lp4 = (const float4*)(logit + (size_t)b * N);
    const int n4 = N >> 2;
    for (int i = tid; i < n4; i += NTH) {
        float4 v = lp4[i];
        unsigned k0 = fkey(v.x), k1 = fkey(v.y), k2 = fkey(v.z), k3 = fkey(v.w);
        ((uint4*)keys)[i] = make_uint4(k0, k1, k2, k3);
        atomicAdd(&hist[k0 >> 20], 1u);
        atomicAdd(&hist[k1 >> 20], 1u);
        atomicAdd(&hist[k2 >> 20], 1u);
        atomicAdd(&hist[k3 >> 20], 1u);
    }
    __syncthreads();

    // ---- Per-thread chunk sums (8 bins each), alias psum onto cand area ----
    unsigned* psum = (unsigned*)cand;
    {
        unsigned s = 0;
        int base = tid * (NBINS / NTH);
        #pragma unroll
        for (int j = 0; j < NBINS / NTH; ++j) s += hist[base + j];
        psum[tid] = s;
    }
    __syncthreads();

    // ---- Warp 0: find largest bin T with count(bins >= T) >= KSEL ----
    if (tid < 32) {
        const int lane = tid;
        unsigned carry = 0;
        for (int g = 15; g >= 0; --g) {
            unsigned v = psum[g * 32 + lane];
            unsigned s = v;
            #pragma unroll
            for (int off = 1; off < 32; off <<= 1) {
                unsigned n = __shfl_down_sync(FULLM, s, off);
                if (lane + off < 32) s += n;
            }
            unsigned gsum = __shfl_sync(FULLM, s, 0);
            if (carry + gsum >= (unsigned)KSEL) {
                unsigned ball = __ballot_sync(FULLM, carry + s >= (unsigned)KSEL);
                int hi = 31 - __clz(ball);
                unsigned s_hi = __shfl_sync(FULLM, s, hi);
                unsigned v_hi = __shfl_sync(FULLM, v, hi);
                if (lane == 0) {
                    unsigned above = carry + s_hi - v_hi;  // count of chunks > C
                    int C = g * 32 + hi;
                    int T = C * 8;
                    for (int w = 7; w >= 0; --w) {
                        above += hist[C * 8 + w];
                        if (above >= (unsigned)KSEL) { T = C * 8 + w; break; }
                    }
                    *s_T = T;
                }
                break;
            }
            carry += gsum;
        }
    }
    __syncthreads();
    const unsigned T = (unsigned)*s_T;

    // ---- Collect candidates with bin >= T (vectorized LDS.128 reads) ----
    for (int i = tid; i < n4; i += NTH) {
        uint4 kk = ((const uint4*)keys)[i];
        unsigned ks[4] = { kk.x, kk.y, kk.z, kk.w };
        #pragma unroll
        for (int q = 0; q < 4; ++q) {
            if ((ks[q] >> 20) >= T) {
                unsigned pos = atomicAdd(s_cnt, 1u);
                if (pos < CAP)
                    cand[pos] = ((unsigned long long)ks[q] << 32) | (unsigned)(~(4 * i + q));
            }
        }
    }
    __syncthreads();
    int cnt = (int)*s_cnt; if (cnt > CAP) cnt = CAP;
    int P = 128; while (P < cnt) P <<= 1;
    for (int i = tid; i < P; i += NTH) if (i >= cnt) cand[i] = 0ULL;
    __syncthreads();

    // ---- Bitonic sort descending (composite = (key, ~idx): stable lower-index first) ----
    for (int k = 2; k <= P; k <<= 1) {
        for (int j = k >> 1; j > 0; j >>= 1) {
            for (int i = tid; i < P; i += NTH) {
                int ixj = i ^ j;
                if (ixj > i) {
                    unsigned long long a = cand[i], c2 = cand[ixj];
                    bool desc = ((i & k) == 0);
                    if (desc ? (a < c2) : (a > c2)) { cand[i] = c2; cand[ixj] = a; }
                }
            }
            __syncthreads();
        }
    }

    const float ih = tsz[2 * b + 0];  // target h
    const float iw = tsz[2 * b + 1];  // target w

    // ---- Per-row decode (R4 verbatim) ----
    if (tid < KSEL) {
        unsigned long long e = cand[tid];
        unsigned key = (unsigned)(e >> 32);
        int idx = (int)(~((unsigned)e));
        unsigned u = (key & 0x80000000u) ? (key ^ 0x80000000u) : ~key;
        float lg = __uint_as_float(u);
        float prob = 1.0f / (1.0f + expf(-lg));
        s_val[tid] = prob;
        s_keep[tid] = prob > 0.1f;

        float bx0, bx1, bx2, bx3;
        if (!bez) {
            const float* rp = raw + ((size_t)b * N + idx) * 4;
            float cx = rp[0], cy = rp[1], bw = rp[2], bh = rp[3];
            bx0 = (cx - 0.5f * bw) * iw;
            bx1 = (cy - 0.5f * bh) * ih;
            bx2 = (cx + 0.5f * bw) * iw;
            bx3 = (cy + 0.5f * bh) * ih;
            if (lvl == 0) {
                bx0 = fminf(fmaxf(bx0, 0.f), iw);
                bx1 = fminf(fmaxf(bx1, 0.f), ih);
                bx2 = fminf(fmaxf(bx2, 0.f), iw);
                bx3 = fminf(fmaxf(bx3, 0.f), ih);
            }
            s_data[tid * 16 + 0] = bx0; s_data[tid * 16 + 1] = bx1;
            s_data[tid * 16 + 2] = bx2; s_data[tid * 16 + 3] = bx3;
        } else {
            const float* rp = raw + ((size_t)b * N + idx) * 16;
            float cpt[16];
            #pragma unroll
            for (int q = 0; q < 8; ++q) {
                cpt[2 * q + 0] = rp[2 * q + 0] * ih;   // tile(tsize,8): even -> h
                cpt[2 * q + 1] = rp[2 * q + 1] * iw;   // odd -> w
            }
            #pragma unroll
            for (int q = 0; q < 16; ++q) s_data[tid * 16 + q] = cpt[q];
            float mn0 = 1e30f, mn1 = 1e30f, mx0 = -1e30f, mx1 = -1e30f;
            #pragma unroll
            for (int s2 = 0; s2 < 10; ++s2) {
                float t  = (float)s2 / 9.0f;
                float ti = 1.0f - t;
                float b0 = ti * ti * ti, b1 = 3.f * t * ti * ti;
                float b2 = 3.f * t * t * ti, b3 = t * t * t;
                float p0 = b0 * cpt[0] + b1 * cpt[2] + b2 * cpt[4]  + b3 * cpt[6];
                float p1 = b0 * cpt[1] + b1 * cpt[3] + b2 * cpt[5]  + b3 * cpt[7];
                float q0 = b0 * cpt[8] + b1 * cpt[10] + b2 * cpt[12] + b3 * cpt[14];
                float q1 = b0 * cpt[9] + b1 * cpt[11] + b2 * cpt[13] + b3 * cpt[15];
                mn0 = fminf(mn0, fminf(p0, q0));
                mn1 = fminf(mn1, fminf(p1, q1));
                mx0 = fmaxf(mx0, fmaxf(p0, q0));
                mx1 = fmaxf(mx1, fmaxf(p1, q1));
            }
            bx0 = mn0; bx1 = mn1; bx2 = mx0; bx3 = mx1;
        }
        s_box[tid * 4 + 0] = bx0; s_box[tid * 4 + 1] = bx1;
        s_box[tid * 4 + 2] = bx2; s_box[tid * 4 + 3] = bx3;
        float area = (bx2 - bx0) * (bx3 - bx1);
        s_area[tid] = area;

        if (lvl > 0) {
            const float* pr = praw + ((size_t)b * PN + idx / ef) * 4;
            float pcx = pr[0], pcy = pr[1], pw = pr[2], ph = pr[3];
            float px0 = (pcx - 0.5f * pw) * iw, py0 = (pcy - 0.5f * ph) * ih;
            float px1 = (pcx + 0.5f * pw) * iw, py1 = (pcy + 0.5f * ph) * ih;
            float ix1 = fmaxf(bx0, px0), iy1 = fmaxf(bx1, py0);
            float ix2 = fminf(bx2, px1), iy2 = fminf(bx3, py1);
            float inter = fmaxf(ix2 - ix1, 0.f) * fmaxf(iy2 - iy1, 0.f);
            float belong = inter / (area + 1e-6f);
            s_bel[tid] = belong;
            s_vld[tid] = belong > 0.6f;
        }
    }
    __syncthreads();

    // ---- Serial reductions (tid 0; R4 verbatim — empirically the fast path) ----
    if (tid == 0) {
        bool any = false;
        for (int r = 0; r < KSEL; ++r) any = any || (s_keep[r] != 0);
        if (!any) s_keep[0] = 1;
        if (lvl > 0) {
            bool anyVK = false;
            float best = -1e38f; int bi = 0;
            for (int r = 0; r < KSEL; ++r) {
                bool kp = s_keep[r] != 0;
                if (kp && s_vld[r]) anyVK = true;
                float v2 = kp ? s_bel[r] : -1e38f;
                if (v2 > best) { best = v2; bi = r; }
            }
            for (int r = 0; r < KSEL; ++r) {
                int m = anyVK ? (s_keep[r] && s_vld[r])
                              : (s_keep[r] && (r == bi));
                s_nk[r] = m;
            }
        } else {
            for (int r = 0; r < KSEL; ++r) s_nk[r] = s_keep[r];
        }
    }
    __syncthreads();   // s_nk visible to the NMS subset

    // ---- Greedy NMS on warps 0-3 (named barrier), barrier only on active rows.
    //      If s_nk[i]==0 the iteration writes nothing, so no barrier is needed;
    //      the check is a uniform broadcast read (convergent branch). ----
    if (tid < 128) {
        for (int i = 0; i < KSEL - 1; ++i) {
            if (s_nk[i]) {
                if (tid > i && tid < KSEL) {
                    float ax0 = s_box[i * 4 + 0], ay0 = s_box[i * 4 + 1];
                    float ax1 = s_box[i * 4 + 2], ay1 = s_box[i * 4 + 3];
                    float bx0 = s_box[tid * 4 + 0], by0 = s_box[tid * 4 + 1];
                    float bx1 = s_box[tid * 4 + 2], by1 = s_box[tid * 4 + 3];
                    float ix0 = fmaxf(ax0, bx0), iy0 = fmaxf(ay0, by0);
                    float ix1 = fminf(ax1, bx1), iy1 = fminf(ay1, by1);
                    float inter = fmaxf(ix1 - ix0, 0.f) * fmaxf(iy1 - iy0, 0.f);
                    float iou = inter / (s_area[i] + s_area[tid] - inter);
                    if (iou > 0.1f) s_nk[tid] = 0;
                }
                asm volatile("bar.sync 1, 128;" ::: "memory");
            }
        }
    }
    __syncthreads();

    // ---- Write outputs (R4 verbatim) ----
    size_t nbd = (size_t)B * 400;   // B*100*4
    size_t nsc = (size_t)B * 100;
    size_t oD, oS, oK;
    if (lvl == 0)      { oD = 0; oS = nbd; oK = nbd + nsc; }
    else if (lvl == 1) { size_t base = nbd + 2 * nsc; oD = base; oS = base + nbd; oK = oS + nsc; }
    else               { size_t base = 2 * (nbd + 2 * nsc); oD = base; oS = base + (size_t)B * 1600; oK = oS + nsc; }

    if (tid < KSEL) {
        bool nk = s_nk[tid] != 0;
        out[oS + (size_t)b * 100 + tid] = nk ? s_val[tid] : 0.f;
        out[oK + (size_t)b * 100 + tid] = nk ? 1.f : 0.f;
        int D = bez ? 16 : 4;
        float* dp = out + oD + ((size_t)b * 100 + tid) * D;
        for (int d2 = 0; d2 < D; ++d2) dp[d2] = nk ? s_data[tid * 16 + d2] : 0.f;
    }
}

extern "C" void kernel_launch(void* const* d_in, const int* in_sizes, int n_in,
                              void* d_out, int out_size) {
    const float* blk_logit = (const float*)d_in[0];
    const float* lin_logit = (const float*)d_in[1];
    const float* chr_logit = (const float*)d_in[2];
    const float* blk_raw   = (const float*)d_in[3];
    const float* lin_raw   = (const float*)d_in[4];
    const float* chr_raw   = (const float*)d_in[5];
    const float* tsz       = (const float*)d_in[6];
    float* out = (float*)d_out;

    int B  = in_sizes[6] / 2;
    int NB = in_sizes[0] / B;
    int NL = in_sizes[1] / B;
    int NC = in_sizes[2] / B;

    cudaFuncSetAttribute(pp_kernel, cudaFuncAttributeMaxDynamicSharedMemorySize, SMEM_BYTES);
    pp_kernel<<<3 * B, NTH, SMEM_BYTES>>>(blk_logit, lin_logit, chr_logit,
                                          blk_raw, lin_raw, chr_raw, tsz, out,
                                          B, NB, NL, NC);
}